// round 14
// baseline (speedup 1.0000x reference)
#include <cuda_runtime.h>
#include <cuda_bf16.h>
#include <math.h>

#define B_ 8
#define N_ 5
#define C_ 256
#define HW_ 4096
#define M_ 32768
#define STG_ (8704 + 10240)
#define SMEMSZ (4 * STG_)   // 4-stage X + W

// ---------------- scratch ----------------------------------------------------
__device__ float          g_sum  [B_*C_*HW_];
__device__ float          g_proj [B_*N_*4*HW_];
__device__ __nv_bfloat16  g_mtb  [N_*B_*C_*HW_];   // [i][b][c][hw]
__device__ __nv_bfloat16  g_htb  [B_*N_*C_*HW_];   // [b][i][c][hw]
__device__ __nv_bfloat16  g_rhb  [N_*B_*C_*HW_];   // [i][b][c][hw]
__device__ __nv_bfloat16  g_u    [N_*B_*C_*HW_];
__device__ __nv_bfloat16  g_Wcatb[512*512];        // [u;r] x [mt|ht]
__device__ __nv_bfloat16  g_Wob  [256*512];        // full w_o (left|right)
__device__ float          g_bcat [768];

// ---------------- streams/events (created pre-checkpoint, reused) ------------
struct HxStreams {
    cudaStream_t s2;
    cudaEvent_t evFork, evPrep, evG1a, evG1b, evJoin;
    HxStreams() {
        cudaStreamCreateWithFlags(&s2, cudaStreamNonBlocking);
        cudaEventCreateWithFlags(&evFork, cudaEventDisableTiming);
        cudaEventCreateWithFlags(&evPrep, cudaEventDisableTiming);
        cudaEventCreateWithFlags(&evG1a, cudaEventDisableTiming);
        cudaEventCreateWithFlags(&evG1b, cudaEventDisableTiming);
        cudaEventCreateWithFlags(&evJoin, cudaEventDisableTiming);
    }
};
static HxStreams g_hx;

// ---------------- asm helpers ------------------------------------------------
__device__ __forceinline__ void ldsmx4(unsigned &r0, unsigned &r1, unsigned &r2, unsigned &r3, unsigned a) {
    asm volatile("ldmatrix.sync.aligned.m8n8.x4.shared.b16 {%0,%1,%2,%3},[%4];"
        : "=r"(r0), "=r"(r1), "=r"(r2), "=r"(r3) : "r"(a));
}
__device__ __forceinline__ void ldsmx4t(unsigned &r0, unsigned &r1, unsigned &r2, unsigned &r3, unsigned a) {
    asm volatile("ldmatrix.sync.aligned.m8n8.x4.trans.shared.b16 {%0,%1,%2,%3},[%4];"
        : "=r"(r0), "=r"(r1), "=r"(r2), "=r"(r3) : "r"(a));
}
__device__ __forceinline__ void mma_bf16(float* d, const unsigned* a, unsigned b0, unsigned b1) {
    asm volatile("mma.sync.aligned.m16n8k16.row.col.f32.bf16.bf16.f32 "
        "{%0,%1,%2,%3},{%4,%5,%6,%7},{%8,%9},{%0,%1,%2,%3};"
        : "+f"(d[0]), "+f"(d[1]), "+f"(d[2]), "+f"(d[3])
        : "r"(a[0]), "r"(a[1]), "r"(a[2]), "r"(a[3]), "r"(b0), "r"(b1));
}
#define CPA16(dst, src) asm volatile("cp.async.cg.shared.global [%0],[%1],16;" :: "r"(dst), "l"(src))
#define CPCOMMIT()      asm volatile("cp.async.commit_group;" ::: "memory")
#define CPWAIT2()       asm volatile("cp.async.wait_group 2;" ::: "memory")

// ---------------- prep: weights -> bf16 --------------------------------------
__global__ void prep_kernel(const float* __restrict__ wu, const float* __restrict__ wr,
                            const float* __restrict__ wo, const float* __restrict__ bu,
                            const float* __restrict__ br, const float* __restrict__ bo) {
    int idx = blockIdx.x * 256 + threadIdx.x;
    if (idx < 512 * 512) {
        int o = idx >> 9, k = idx & 511;
        float v = (o < 256) ? wu[o * 512 + k] : wr[(o - 256) * 512 + k];
        g_Wcatb[idx] = __float2bfloat16(v);
    }
    if (idx < 256 * 512)
        g_Wob[idx] = __float2bfloat16(wo[idx]);
    if (idx < 768)
        g_bcat[idx] = (idx < 256) ? bu[idx] : (idx < 512 ? br[idx - 256] : bo[idx - 512]);
}

// ---------------- sum over frames + 20 gate projections + htb ----------------
__global__ void sumproj_kernel(const float* __restrict__ inp, const float* __restrict__ wgt_w) {
    __shared__ float wsm[4 * 256];
    int tid = threadIdx.x;
    for (int t = tid; t < 1024; t += 256) wsm[t] = wgt_w[t];
    __syncthreads();
    int m  = blockIdx.x * 256 + tid;
    int b  = m >> 12;
    int hw = m & 4095;
    float pj[N_][4];
#pragma unroll
    for (int j = 0; j < N_; j++)
#pragma unroll
        for (int p = 0; p < 4; p++) pj[j][p] = 0.f;
    const float* base = inp + (size_t)b * N_ * C_ * HW_ + hw;
#pragma unroll 2
    for (int c = 0; c < C_; c++) {
        float w0 = wsm[c], w1 = wsm[256 + c], w2 = wsm[512 + c], w3 = wsm[768 + c];
        float s = 0.f;
#pragma unroll
        for (int j = 0; j < N_; j++) {
            float v = base[(j * C_ + c) * HW_];
            s += v;
            pj[j][0] += v * w0; pj[j][1] += v * w1;
            pj[j][2] += v * w2; pj[j][3] += v * w3;
            g_htb[((size_t)(b * N_ + j) * C_ + c) * HW_ + hw] = __float2bfloat16(v);
        }
        g_sum[((b << 8) + c) * HW_ + hw] = s;
    }
#pragma unroll
    for (int j = 0; j < N_; j++)
#pragma unroll
        for (int p = 0; p < 4; p++)
            g_proj[(((b * N_ + j) << 2) + p) * HW_ + hw] = pj[j][p];
}

// ---------------- m_t(bf16), all i; 2 hw/thread (reads bf16 ht) --------------
__global__ void mtht_kernel(const float* __restrict__ inp) {
    int t2 = blockIdx.x * 256 + threadIdx.x;    // pair index over [i][b][c][hw/2]
    int hw = (t2 & 2047) * 2;
    int c  = (t2 >> 11) & 255;
    int b  = (t2 >> 19) & 7;
    int i  = t2 >> 22;
    int p  = c & 3;
    int jp = (p < i) ? p : p + 1;
    float2 a0 = *(const float2*)&g_proj[(((b * N_ + i)  << 2) + p) * HW_ + hw];
    float2 a1 = *(const float2*)&g_proj[(((b * N_ + jp) << 2) + p) * HW_ + hw];
    __nv_bfloat162 htb2 = *(const __nv_bfloat162*)
        &g_htb[((size_t)(b * N_ + i) * C_ + c) * HW_ + hw];
    float2 sv = *(const float2*)&g_sum[((b << 8) + c) * HW_ + hw];
    float g0 = 1.f / (1.f + expf(-(a0.x - a1.x)));
    float g1 = 1.f / (1.f + expf(-(a0.y - a1.y)));
    __nv_bfloat162 mt2;
    mt2.x = __float2bfloat16(g0 * (sv.x - __bfloat162float(htb2.x)));
    mt2.y = __float2bfloat16(g1 * (sv.y - __bfloat162float(htb2.y)));
    *(__nv_bfloat162*)&g_mtb[((size_t)(i * B_ + b) * C_ + c) * HW_ + hw] = mt2;
}

// ---------------- GEMM1 (bf16): [u;rh] = Wcat @ [m_t; h_t] -------------------
__global__ __launch_bounds__(256, 2)
void gemm1_kernel(const float* __restrict__ inp, int i0) {
    extern __shared__ __align__(16) unsigned char smem_dyn[];
    const int tid  = threadIdx.x;
    const int lane = tid & 31, wid = tid >> 5;
    const int wm = wid >> 2, wn = wid & 3;
    const int r_ = lane >> 2, c_ = lane & 3;
    const int i     = i0 + blockIdx.z;
    const int nBase = blockIdx.x * 128;
    const int mBase = blockIdx.y * 128;
    const int b = mBase >> 12, hwB = mBase & 4095;

    unsigned sXu = (unsigned)__cvta_generic_to_shared(smem_dyn);
    unsigned sWu = sXu + 4 * 8704;

    const int kr = tid >> 3, c0 = tid & 7;       // X staging
    const int nrow = tid >> 1, ch = tid & 1;     // W staging

    const __nv_bfloat16* mtB = g_mtb + (size_t)(i * B_ + b) * C_ * HW_ + hwB;
    const __nv_bfloat16* htB = g_htb + (size_t)(b * N_ + i) * C_ * HW_ + hwB;
    const __nv_bfloat16* wB  = g_Wcatb + (size_t)(nBase + nrow) * 512;

    auto issue = [&](int tt) {
        int st = tt & 3, kb = tt * 32;
        const __nv_bfloat16* asrc = (kb < 256)
            ? (mtB + (size_t)(kb + kr) * HW_)
            : (htB + (size_t)(kb - 256 + kr) * HW_);
        unsigned xd = sXu + st * 8704 + kr * 272;
        CPA16(xd + c0 * 16,       asrc + c0 * 8);
        CPA16(xd + (c0 + 8) * 16, asrc + (c0 + 8) * 8);
        const __nv_bfloat16* wsrc = wB + kb;
        unsigned wd = sWu + st * 10240 + nrow * 80;
        CPA16(wd + ch * 16,       wsrc + ch * 8);
        CPA16(wd + (ch + 2) * 16, wsrc + (ch + 2) * 8);
    };

    float acc[4][4][4];
#pragma unroll
    for (int mt = 0; mt < 4; mt++)
#pragma unroll
        for (int nt = 0; nt < 4; nt++)
#pragma unroll
            for (int q = 0; q < 4; q++) acc[mt][nt][q] = 0.f;

    const int rowA = (lane & 7) + ((lane >> 4) << 3);
    const int colA = ((lane >> 3) & 1) << 3;
    const unsigned aAddr0 = sXu + rowA * 272 + (wm * 64 + colA) * 2;
    const int nOffB = (((lane >> 4) & 1) << 3) + (lane & 7);
    const int kOffB = ((lane >> 3) & 1) << 3;
    const unsigned bAddr0 = sWu + (wn * 32 + nOffB) * 80 + kOffB * 2;

    const int NK = 16;   // K = 512
#pragma unroll
    for (int tt = 0; tt < 3; tt++) { issue(tt); CPCOMMIT(); }
#pragma unroll 1
    for (int t = 0; t < NK; t++) {
        CPWAIT2();
        __syncthreads();
        if (t + 3 < NK) issue(t + 3);
        CPCOMMIT();
        const int st = t & 3;
        const unsigned aB = aAddr0 + st * 8704;
        const unsigned bB = bAddr0 + st * 10240;
#pragma unroll
        for (int kk = 0; kk < 2; kk++) {
            unsigned af[4][4], bfm[2][4];
#pragma unroll
            for (int mt = 0; mt < 4; mt++)
                ldsmx4t(af[mt][0], af[mt][1], af[mt][2], af[mt][3],
                        aB + kk * (16 * 272) + mt * 32);
#pragma unroll
            for (int np = 0; np < 2; np++)
                ldsmx4(bfm[np][0], bfm[np][1], bfm[np][2], bfm[np][3],
                       bB + kk * 32 + np * (16 * 80));
#pragma unroll
            for (int mt = 0; mt < 4; mt++)
#pragma unroll
                for (int nt = 0; nt < 4; nt++)
                    mma_bf16(acc[mt][nt], af[mt],
                             bfm[nt >> 1][(nt & 1) * 2], bfm[nt >> 1][(nt & 1) * 2 + 1]);
        }
    }

    const int seg = nBase >> 8;   // 0=u, 1=rh
    const float* htf = inp + (size_t)(b * N_ + i) * C_ * HW_;
    const size_t obase = (size_t)(i * B_ + b) * C_;
#pragma unroll
    for (int mt = 0; mt < 4; mt++)
#pragma unroll
        for (int nt = 0; nt < 4; nt++) {
            int px0 = hwB + wm * 64 + mt * 16 + r_;
            int ch0 = nBase + wn * 32 + nt * 8 + c_ * 2;
#pragma unroll
            for (int q = 0; q < 4; q++) {
                int o  = ch0 + (q & 1);
                int hw = px0 + ((q >> 1) << 3);
                float v = acc[mt][nt][q] + g_bcat[o];
                if (seg == 0) {
                    g_u[(obase + o) * HW_ + hw] = __float2bfloat16(1.f / (1.f + expf(-v)));
                } else {
                    int c = o - 256;
                    float ht = htf[(size_t)c * HW_ + hw];
                    g_rhb[(obase + c) * HW_ + hw] = __float2bfloat16(ht / (1.f + expf(-v)));
                }
            }
        }
}

// ---------------- GEMM2 (bf16): o_pre = Wo @ [m_t; rh] + b_o; combine --------
__global__ __launch_bounds__(256, 2)
void gemm2_kernel(const float* __restrict__ inp, const float* __restrict__ gamma,
                  float* __restrict__ out, int i0) {
    extern __shared__ __align__(16) unsigned char smem_dyn[];
    const int tid  = threadIdx.x;
    const int lane = tid & 31, wid = tid >> 5;
    const int wm = wid >> 2, wn = wid & 3;
    const int r_ = lane >> 2, c_ = lane & 3;
    const int i     = i0 + blockIdx.z;
    const int nBase = blockIdx.x * 128;
    const int mBase = blockIdx.y * 128;
    const int b = mBase >> 12, hwB = mBase & 4095;

    unsigned sXu = (unsigned)__cvta_generic_to_shared(smem_dyn);
    unsigned sWu = sXu + 4 * 8704;

    const int kr = tid >> 3, c0 = tid & 7;
    const int nrow = tid >> 1, ch = tid & 1;

    const __nv_bfloat16* mtB = g_mtb + (size_t)(i * B_ + b) * C_ * HW_ + hwB;
    const __nv_bfloat16* rhB = g_rhb + (size_t)(i * B_ + b) * C_ * HW_ + hwB;
    const __nv_bfloat16* wB  = g_Wob + (size_t)(nBase + nrow) * 512;

    auto issue = [&](int tt) {
        int st = tt & 3, kb = tt * 32;
        const __nv_bfloat16* asrc = (kb < 256)
            ? (mtB + (size_t)(kb + kr) * HW_)
            : (rhB + (size_t)(kb - 256 + kr) * HW_);
        unsigned xd = sXu + st * 8704 + kr * 272;
        CPA16(xd + c0 * 16,       asrc + c0 * 8);
        CPA16(xd + (c0 + 8) * 16, asrc + (c0 + 8) * 8);
        const __nv_bfloat16* wsrc = wB + kb;
        unsigned wd = sWu + st * 10240 + nrow * 80;
        CPA16(wd + ch * 16,       wsrc + ch * 8);
        CPA16(wd + (ch + 2) * 16, wsrc + (ch + 2) * 8);
    };

    float acc[4][4][4];
#pragma unroll
    for (int mt = 0; mt < 4; mt++)
#pragma unroll
        for (int nt = 0; nt < 4; nt++)
#pragma unroll
            for (int q = 0; q < 4; q++) acc[mt][nt][q] = 0.f;

    const int rowA = (lane & 7) + ((lane >> 4) << 3);
    const int colA = ((lane >> 3) & 1) << 3;
    const unsigned aAddr0 = sXu + rowA * 272 + (wm * 64 + colA) * 2;
    const int nOffB = (((lane >> 4) & 1) << 3) + (lane & 7);
    const int kOffB = ((lane >> 3) & 1) << 3;
    const unsigned bAddr0 = sWu + (wn * 32 + nOffB) * 80 + kOffB * 2;

    const int NK = 16;   // K = 512: [m_t ; rh]
#pragma unroll
    for (int tt = 0; tt < 3; tt++) { issue(tt); CPCOMMIT(); }
#pragma unroll 1
    for (int t = 0; t < NK; t++) {
        CPWAIT2();
        __syncthreads();
        if (t + 3 < NK) issue(t + 3);
        CPCOMMIT();
        const int st = t & 3;
        const unsigned aB = aAddr0 + st * 8704;
        const unsigned bB = bAddr0 + st * 10240;
#pragma unroll
        for (int kk = 0; kk < 2; kk++) {
            unsigned af[4][4], bfm[2][4];
#pragma unroll
            for (int mt = 0; mt < 4; mt++)
                ldsmx4t(af[mt][0], af[mt][1], af[mt][2], af[mt][3],
                        aB + kk * (16 * 272) + mt * 32);
#pragma unroll
            for (int np = 0; np < 2; np++)
                ldsmx4(bfm[np][0], bfm[np][1], bfm[np][2], bfm[np][3],
                       bB + kk * 32 + np * (16 * 80));
#pragma unroll
            for (int mt = 0; mt < 4; mt++)
#pragma unroll
                for (int nt = 0; nt < 4; nt++)
                    mma_bf16(acc[mt][nt], af[mt],
                             bfm[nt >> 1][(nt & 1) * 2], bfm[nt >> 1][(nt & 1) * 2 + 1]);
        }
    }

    const float gm = gamma[0];
    const float* htf = inp + (size_t)(b * N_ + i) * C_ * HW_;
    const size_t obase = (size_t)(i * B_ + b) * C_;
#pragma unroll
    for (int mt = 0; mt < 4; mt++)
#pragma unroll
        for (int nt = 0; nt < 4; nt++) {
            int px0 = hwB + wm * 64 + mt * 16 + r_;
            int ch0 = nBase + wn * 32 + nt * 8 + c_ * 2;
#pragma unroll
            for (int q = 0; q < 4; q++) {
                int o  = ch0 + (q & 1);
                int hw = px0 + ((q >> 1) << 3);
                size_t idx = (obase + o) * HW_ + hw;
                float opre = acc[mt][nt][q] + g_bcat[512 + o];
                float u  = __bfloat162float(g_u[idx]);
                float ht = htf[(size_t)o * HW_ + hw];
                float hn = ht * (1.f - u) + tanhf(opre) * u;
                out[((size_t)(b * N_ + i) * C_ + o) * HW_ + hw] = hn * gm + ht;
            }
        }
}

// ---------------- launch: 2-chunk fork/join overlap --------------------------
extern "C" void kernel_launch(void* const* d_in, const int* in_sizes, int n_in,
                              void* d_out, int out_size) {
    const float* inp   = (const float*)d_in[0];
    const float* wgt_w = (const float*)d_in[1];
    const float* w_r   = (const float*)d_in[2];
    const float* b_r   = (const float*)d_in[3];
    const float* w_u   = (const float*)d_in[4];
    const float* b_u   = (const float*)d_in[5];
    const float* w_o   = (const float*)d_in[6];
    const float* b_o   = (const float*)d_in[7];
    const float* gamma = (const float*)d_in[8];
    float* out = (float*)d_out;

    cudaFuncSetAttribute(gemm1_kernel, cudaFuncAttributeMaxDynamicSharedMemorySize, SMEMSZ);
    cudaFuncSetAttribute(gemm2_kernel, cudaFuncAttributeMaxDynamicSharedMemorySize, SMEMSZ);

    // fork s2; prep (weights only) overlaps sumproj
    cudaEventRecord(g_hx.evFork, 0);
    cudaStreamWaitEvent(g_hx.s2, g_hx.evFork, 0);
    prep_kernel<<<1024, 256, 0, g_hx.s2>>>(w_u, w_r, w_o, b_u, b_r, b_o);
    cudaEventRecord(g_hx.evPrep, g_hx.s2);

    sumproj_kernel<<<M_ / 256, 256>>>(inp, wgt_w);
    mtht_kernel<<<(N_ * B_ * C_ * HW_) / 512, 256>>>(inp);
    cudaStreamWaitEvent(0, g_hx.evPrep, 0);

    // chunk A: i = 0..2 ; chunk B: i = 3..4
    gemm1_kernel<<<dim3(4, 256, 3), 256, SMEMSZ>>>(inp, 0);
    cudaEventRecord(g_hx.evG1a, 0);
    gemm1_kernel<<<dim3(4, 256, 2), 256, SMEMSZ>>>(inp, 3);
    cudaEventRecord(g_hx.evG1b, 0);

    cudaStreamWaitEvent(g_hx.s2, g_hx.evG1a, 0);
    gemm2_kernel<<<dim3(2, 256, 3), 256, SMEMSZ, g_hx.s2>>>(inp, gamma, out, 0);
    cudaStreamWaitEvent(g_hx.s2, g_hx.evG1b, 0);
    gemm2_kernel<<<dim3(2, 256, 2), 256, SMEMSZ, g_hx.s2>>>(inp, gamma, out, 3);

    cudaEventRecord(g_hx.evJoin, g_hx.s2);
    cudaStreamWaitEvent(0, g_hx.evJoin, 0);
}

// round 15
// speedup vs baseline: 1.1184x; 1.1184x over previous
#include <cuda_runtime.h>
#include <cuda_bf16.h>
#include <math.h>

#define B_ 8
#define N_ 5
#define C_ 256
#define HW_ 4096
#define M_ 32768
#define STG_ (8704 + 10240)
#define SMEMSZ (4 * STG_)   // 4-stage X + W

// ---------------- scratch ----------------------------------------------------
__device__ float          g_sum  [B_*C_*HW_];
__device__ float          g_proj [B_*N_*4*HW_];
__device__ __nv_bfloat16  g_mtb  [N_*B_*C_*HW_];   // [i][b][c][hw]
__device__ __nv_bfloat16  g_htb  [B_*N_*C_*HW_];   // [b][i][c][hw]
__device__ __nv_bfloat16  g_rhb  [N_*B_*C_*HW_];   // [i][b][c][hw]
__device__ __nv_bfloat16  g_u    [N_*B_*C_*HW_];
__device__ __nv_bfloat16  g_Wcatb[512*512];        // [u;r] x [mt|ht]
__device__ __nv_bfloat16  g_Wob  [256*512];        // full w_o (left|right)
__device__ float          g_bcat [768];

// ---------------- asm helpers ------------------------------------------------
__device__ __forceinline__ void ldsmx4(unsigned &r0, unsigned &r1, unsigned &r2, unsigned &r3, unsigned a) {
    asm volatile("ldmatrix.sync.aligned.m8n8.x4.shared.b16 {%0,%1,%2,%3},[%4];"
        : "=r"(r0), "=r"(r1), "=r"(r2), "=r"(r3) : "r"(a));
}
__device__ __forceinline__ void ldsmx4t(unsigned &r0, unsigned &r1, unsigned &r2, unsigned &r3, unsigned a) {
    asm volatile("ldmatrix.sync.aligned.m8n8.x4.trans.shared.b16 {%0,%1,%2,%3},[%4];"
        : "=r"(r0), "=r"(r1), "=r"(r2), "=r"(r3) : "r"(a));
}
__device__ __forceinline__ void mma_bf16(float* d, const unsigned* a, unsigned b0, unsigned b1) {
    asm volatile("mma.sync.aligned.m16n8k16.row.col.f32.bf16.bf16.f32 "
        "{%0,%1,%2,%3},{%4,%5,%6,%7},{%8,%9},{%0,%1,%2,%3};"
        : "+f"(d[0]), "+f"(d[1]), "+f"(d[2]), "+f"(d[3])
        : "r"(a[0]), "r"(a[1]), "r"(a[2]), "r"(a[3]), "r"(b0), "r"(b1));
}
#define CPA16(dst, src) asm volatile("cp.async.cg.shared.global [%0],[%1],16;" :: "r"(dst), "l"(src))
#define CPCOMMIT()      asm volatile("cp.async.commit_group;" ::: "memory")
#define CPWAIT2()       asm volatile("cp.async.wait_group 2;" ::: "memory")

// ---------------- prep: weights -> bf16 --------------------------------------
__global__ void prep_kernel(const float* __restrict__ wu, const float* __restrict__ wr,
                            const float* __restrict__ wo, const float* __restrict__ bu,
                            const float* __restrict__ br, const float* __restrict__ bo) {
    int idx = blockIdx.x * 256 + threadIdx.x;
    if (idx < 512 * 512) {
        int o = idx >> 9, k = idx & 511;
        float v = (o < 256) ? wu[o * 512 + k] : wr[(o - 256) * 512 + k];
        g_Wcatb[idx] = __float2bfloat16(v);
    }
    if (idx < 256 * 512)
        g_Wob[idx] = __float2bfloat16(wo[idx]);
    if (idx < 768)
        g_bcat[idx] = (idx < 256) ? bu[idx] : (idx < 512 ? br[idx - 256] : bo[idx - 512]);
}

// ---------------- sumproj: 512 threads, c-split halves, emits htb ------------
// 128 blocks x 512 thr. px = tid&255 (256 px/block); half = tid>>8 handles
// 128 channels. pj reduced across halves via smem; sum/htb written per-c.
__global__ __launch_bounds__(512)
void sumproj_kernel(const float* __restrict__ inp, const float* __restrict__ wgt_w) {
    __shared__ float wsm[4 * 256];
    __shared__ float red[20 * 256];
    const int tid = threadIdx.x;
    const int px  = tid & 255;
    const int half = tid >> 8;
    for (int t = tid; t < 1024; t += 512) wsm[t] = wgt_w[t];
    __syncthreads();
    const int m  = blockIdx.x * 256 + px;
    const int b  = m >> 12;
    const int hw = m & 4095;

    float pj[N_][4];
#pragma unroll
    for (int j = 0; j < N_; j++)
#pragma unroll
        for (int p = 0; p < 4; p++) pj[j][p] = 0.f;

    const float* base = inp + (size_t)b * N_ * C_ * HW_ + hw;
    const int c0 = half * 128;
#pragma unroll 2
    for (int cc = 0; cc < 128; cc++) {
        int c = c0 + cc;
        float w0 = wsm[c], w1 = wsm[256 + c], w2 = wsm[512 + c], w3 = wsm[768 + c];
        float s = 0.f;
#pragma unroll
        for (int j = 0; j < N_; j++) {
            float v = base[(j * C_ + c) * HW_];
            s += v;
            pj[j][0] += v * w0; pj[j][1] += v * w1;
            pj[j][2] += v * w2; pj[j][3] += v * w3;
            g_htb[((size_t)(b * N_ + j) * C_ + c) * HW_ + hw] = __float2bfloat16(v);
        }
        g_sum[((b << 8) + c) * HW_ + hw] = s;
    }
    if (half) {
#pragma unroll
        for (int j = 0; j < N_; j++)
#pragma unroll
            for (int p = 0; p < 4; p++)
                red[(j * 4 + p) * 256 + px] = pj[j][p];
    }
    __syncthreads();
    if (!half) {
#pragma unroll
        for (int j = 0; j < N_; j++)
#pragma unroll
            for (int p = 0; p < 4; p++) {
                float v = pj[j][p] + red[(j * 4 + p) * 256 + px];
                g_proj[(((b * N_ + j) << 2) + p) * HW_ + hw] = v;
            }
    }
}

// ---------------- m_t(bf16), all i; 2 hw/thread (reads bf16 ht) --------------
__global__ void mtht_kernel() {
    int t2 = blockIdx.x * 256 + threadIdx.x;    // pair index over [i][b][c][hw/2]
    int hw = (t2 & 2047) * 2;
    int c  = (t2 >> 11) & 255;
    int b  = (t2 >> 19) & 7;
    int i  = t2 >> 22;
    int p  = c & 3;
    int jp = (p < i) ? p : p + 1;
    float2 a0 = *(const float2*)&g_proj[(((b * N_ + i)  << 2) + p) * HW_ + hw];
    float2 a1 = *(const float2*)&g_proj[(((b * N_ + jp) << 2) + p) * HW_ + hw];
    __nv_bfloat162 htb2 = *(const __nv_bfloat162*)
        &g_htb[((size_t)(b * N_ + i) * C_ + c) * HW_ + hw];
    float2 sv = *(const float2*)&g_sum[((b << 8) + c) * HW_ + hw];
    float g0 = 1.f / (1.f + expf(-(a0.x - a1.x)));
    float g1 = 1.f / (1.f + expf(-(a0.y - a1.y)));
    __nv_bfloat162 mt2;
    mt2.x = __float2bfloat16(g0 * (sv.x - __bfloat162float(htb2.x)));
    mt2.y = __float2bfloat16(g1 * (sv.y - __bfloat162float(htb2.y)));
    *(__nv_bfloat162*)&g_mtb[((size_t)(i * B_ + b) * C_ + c) * HW_ + hw] = mt2;
}

// ---------------- GEMM1 (bf16): [u;rh] = Wcat @ [m_t; h_t] -------------------
// CTA tile 128px x 128ch, 4-stage cp.async ring, 8 warps x (64x32), K=512.
__global__ __launch_bounds__(256, 2)
void gemm1_kernel(const float* __restrict__ inp) {
    extern __shared__ __align__(16) unsigned char smem_dyn[];
    const int tid  = threadIdx.x;
    const int lane = tid & 31, wid = tid >> 5;
    const int wm = wid >> 2, wn = wid & 3;
    const int r_ = lane >> 2, c_ = lane & 3;
    const int i     = blockIdx.z;
    const int nBase = blockIdx.x * 128;
    const int mBase = blockIdx.y * 128;
    const int b = mBase >> 12, hwB = mBase & 4095;

    unsigned sXu = (unsigned)__cvta_generic_to_shared(smem_dyn);
    unsigned sWu = sXu + 4 * 8704;

    const int kr = tid >> 3, c0 = tid & 7;       // X staging
    const int nrow = tid >> 1, ch = tid & 1;     // W staging

    const __nv_bfloat16* mtB = g_mtb + (size_t)(i * B_ + b) * C_ * HW_ + hwB;
    const __nv_bfloat16* htB = g_htb + (size_t)(b * N_ + i) * C_ * HW_ + hwB;
    const __nv_bfloat16* wB  = g_Wcatb + (size_t)(nBase + nrow) * 512;

    auto issue = [&](int tt) {
        int st = tt & 3, kb = tt * 32;
        const __nv_bfloat16* asrc = (kb < 256)
            ? (mtB + (size_t)(kb + kr) * HW_)
            : (htB + (size_t)(kb - 256 + kr) * HW_);
        unsigned xd = sXu + st * 8704 + kr * 272;
        CPA16(xd + c0 * 16,       asrc + c0 * 8);
        CPA16(xd + (c0 + 8) * 16, asrc + (c0 + 8) * 8);
        const __nv_bfloat16* wsrc = wB + kb;
        unsigned wd = sWu + st * 10240 + nrow * 80;
        CPA16(wd + ch * 16,       wsrc + ch * 8);
        CPA16(wd + (ch + 2) * 16, wsrc + (ch + 2) * 8);
    };

    float acc[4][4][4];
#pragma unroll
    for (int mt = 0; mt < 4; mt++)
#pragma unroll
        for (int nt = 0; nt < 4; nt++)
#pragma unroll
            for (int q = 0; q < 4; q++) acc[mt][nt][q] = 0.f;

    const int rowA = (lane & 7) + ((lane >> 4) << 3);
    const int colA = ((lane >> 3) & 1) << 3;
    const unsigned aAddr0 = sXu + rowA * 272 + (wm * 64 + colA) * 2;
    const int nOffB = (((lane >> 4) & 1) << 3) + (lane & 7);
    const int kOffB = ((lane >> 3) & 1) << 3;
    const unsigned bAddr0 = sWu + (wn * 32 + nOffB) * 80 + kOffB * 2;

    const int NK = 16;   // K = 512
#pragma unroll
    for (int tt = 0; tt < 3; tt++) { issue(tt); CPCOMMIT(); }
#pragma unroll 1
    for (int t = 0; t < NK; t++) {
        CPWAIT2();
        __syncthreads();
        if (t + 3 < NK) issue(t + 3);
        CPCOMMIT();
        const int st = t & 3;
        const unsigned aB = aAddr0 + st * 8704;
        const unsigned bB = bAddr0 + st * 10240;
#pragma unroll
        for (int kk = 0; kk < 2; kk++) {
            unsigned af[4][4], bfm[2][4];
#pragma unroll
            for (int mt = 0; mt < 4; mt++)
                ldsmx4t(af[mt][0], af[mt][1], af[mt][2], af[mt][3],
                        aB + kk * (16 * 272) + mt * 32);
#pragma unroll
            for (int np = 0; np < 2; np++)
                ldsmx4(bfm[np][0], bfm[np][1], bfm[np][2], bfm[np][3],
                       bB + kk * 32 + np * (16 * 80));
#pragma unroll
            for (int mt = 0; mt < 4; mt++)
#pragma unroll
                for (int nt = 0; nt < 4; nt++)
                    mma_bf16(acc[mt][nt], af[mt],
                             bfm[nt >> 1][(nt & 1) * 2], bfm[nt >> 1][(nt & 1) * 2 + 1]);
        }
    }

    const int seg = nBase >> 8;   // 0=u, 1=rh
    const float* htf = inp + (size_t)(b * N_ + i) * C_ * HW_;
    const size_t obase = (size_t)(i * B_ + b) * C_;
#pragma unroll
    for (int mt = 0; mt < 4; mt++)
#pragma unroll
        for (int nt = 0; nt < 4; nt++) {
            int px0 = hwB + wm * 64 + mt * 16 + r_;
            int ch0 = nBase + wn * 32 + nt * 8 + c_ * 2;
#pragma unroll
            for (int q = 0; q < 4; q++) {
                int o  = ch0 + (q & 1);
                int hw = px0 + ((q >> 1) << 3);
                float v = acc[mt][nt][q] + g_bcat[o];
                if (seg == 0) {
                    g_u[(obase + o) * HW_ + hw] = __float2bfloat16(1.f / (1.f + expf(-v)));
                } else {
                    int c = o - 256;
                    float ht = htf[(size_t)c * HW_ + hw];
                    g_rhb[(obase + c) * HW_ + hw] = __float2bfloat16(ht / (1.f + expf(-v)));
                }
            }
        }
}

// ---------------- GEMM2 (bf16): o_pre = Wo @ [m_t; rh] + b_o; combine --------
__global__ __launch_bounds__(256, 2)
void gemm2_kernel(const float* __restrict__ inp, const float* __restrict__ gamma,
                  float* __restrict__ out) {
    extern __shared__ __align__(16) unsigned char smem_dyn[];
    const int tid  = threadIdx.x;
    const int lane = tid & 31, wid = tid >> 5;
    const int wm = wid >> 2, wn = wid & 3;
    const int r_ = lane >> 2, c_ = lane & 3;
    const int i     = blockIdx.z;
    const int nBase = blockIdx.x * 128;
    const int mBase = blockIdx.y * 128;
    const int b = mBase >> 12, hwB = mBase & 4095;

    unsigned sXu = (unsigned)__cvta_generic_to_shared(smem_dyn);
    unsigned sWu = sXu + 4 * 8704;

    const int kr = tid >> 3, c0 = tid & 7;
    const int nrow = tid >> 1, ch = tid & 1;

    const __nv_bfloat16* mtB = g_mtb + (size_t)(i * B_ + b) * C_ * HW_ + hwB;
    const __nv_bfloat16* rhB = g_rhb + (size_t)(i * B_ + b) * C_ * HW_ + hwB;
    const __nv_bfloat16* wB  = g_Wob + (size_t)(nBase + nrow) * 512;

    auto issue = [&](int tt) {
        int st = tt & 3, kb = tt * 32;
        const __nv_bfloat16* asrc = (kb < 256)
            ? (mtB + (size_t)(kb + kr) * HW_)
            : (rhB + (size_t)(kb - 256 + kr) * HW_);
        unsigned xd = sXu + st * 8704 + kr * 272;
        CPA16(xd + c0 * 16,       asrc + c0 * 8);
        CPA16(xd + (c0 + 8) * 16, asrc + (c0 + 8) * 8);
        const __nv_bfloat16* wsrc = wB + kb;
        unsigned wd = sWu + st * 10240 + nrow * 80;
        CPA16(wd + ch * 16,       wsrc + ch * 8);
        CPA16(wd + (ch + 2) * 16, wsrc + (ch + 2) * 8);
    };

    float acc[4][4][4];
#pragma unroll
    for (int mt = 0; mt < 4; mt++)
#pragma unroll
        for (int nt = 0; nt < 4; nt++)
#pragma unroll
            for (int q = 0; q < 4; q++) acc[mt][nt][q] = 0.f;

    const int rowA = (lane & 7) + ((lane >> 4) << 3);
    const int colA = ((lane >> 3) & 1) << 3;
    const unsigned aAddr0 = sXu + rowA * 272 + (wm * 64 + colA) * 2;
    const int nOffB = (((lane >> 4) & 1) << 3) + (lane & 7);
    const int kOffB = ((lane >> 3) & 1) << 3;
    const unsigned bAddr0 = sWu + (wn * 32 + nOffB) * 80 + kOffB * 2;

    const int NK = 16;   // K = 512: [m_t ; rh]
#pragma unroll
    for (int tt = 0; tt < 3; tt++) { issue(tt); CPCOMMIT(); }
#pragma unroll 1
    for (int t = 0; t < NK; t++) {
        CPWAIT2();
        __syncthreads();
        if (t + 3 < NK) issue(t + 3);
        CPCOMMIT();
        const int st = t & 3;
        const unsigned aB = aAddr0 + st * 8704;
        const unsigned bB = bAddr0 + st * 10240;
#pragma unroll
        for (int kk = 0; kk < 2; kk++) {
            unsigned af[4][4], bfm[2][4];
#pragma unroll
            for (int mt = 0; mt < 4; mt++)
                ldsmx4t(af[mt][0], af[mt][1], af[mt][2], af[mt][3],
                        aB + kk * (16 * 272) + mt * 32);
#pragma unroll
            for (int np = 0; np < 2; np++)
                ldsmx4(bfm[np][0], bfm[np][1], bfm[np][2], bfm[np][3],
                       bB + kk * 32 + np * (16 * 80));
#pragma unroll
            for (int mt = 0; mt < 4; mt++)
#pragma unroll
                for (int nt = 0; nt < 4; nt++)
                    mma_bf16(acc[mt][nt], af[mt],
                             bfm[nt >> 1][(nt & 1) * 2], bfm[nt >> 1][(nt & 1) * 2 + 1]);
        }
    }

    const float gm = gamma[0];
    const float* htf = inp + (size_t)(b * N_ + i) * C_ * HW_;
    const size_t obase = (size_t)(i * B_ + b) * C_;
#pragma unroll
    for (int mt = 0; mt < 4; mt++)
#pragma unroll
        for (int nt = 0; nt < 4; nt++) {
            int px0 = hwB + wm * 64 + mt * 16 + r_;
            int ch0 = nBase + wn * 32 + nt * 8 + c_ * 2;
#pragma unroll
            for (int q = 0; q < 4; q++) {
                int o  = ch0 + (q & 1);
                int hw = px0 + ((q >> 1) << 3);
                size_t idx = (obase + o) * HW_ + hw;
                float opre = acc[mt][nt][q] + g_bcat[512 + o];
                float u  = __bfloat162float(g_u[idx]);
                float ht = htf[(size_t)o * HW_ + hw];
                float hn = ht * (1.f - u) + tanhf(opre) * u;
                out[((size_t)(b * N_ + i) * C_ + o) * HW_ + hw] = hn * gm + ht;
            }
        }
}

// ---------------- launch (single stream) -------------------------------------
extern "C" void kernel_launch(void* const* d_in, const int* in_sizes, int n_in,
                              void* d_out, int out_size) {
    const float* inp   = (const float*)d_in[0];
    const float* wgt_w = (const float*)d_in[1];
    const float* w_r   = (const float*)d_in[2];
    const float* b_r   = (const float*)d_in[3];
    const float* w_u   = (const float*)d_in[4];
    const float* b_u   = (const float*)d_in[5];
    const float* w_o   = (const float*)d_in[6];
    const float* b_o   = (const float*)d_in[7];
    const float* gamma = (const float*)d_in[8];
    float* out = (float*)d_out;

    cudaFuncSetAttribute(gemm1_kernel, cudaFuncAttributeMaxDynamicSharedMemorySize, SMEMSZ);
    cudaFuncSetAttribute(gemm2_kernel, cudaFuncAttributeMaxDynamicSharedMemorySize, SMEMSZ);

    prep_kernel<<<1024, 256>>>(w_u, w_r, w_o, b_u, b_r, b_o);
    sumproj_kernel<<<M_ / 256, 512>>>(inp, wgt_w);
    mtht_kernel<<<(N_ * B_ * C_ * HW_) / 512, 256>>>();
    gemm1_kernel<<<dim3(4, 256, 5), 256, SMEMSZ>>>(inp);
    gemm2_kernel<<<dim3(2, 256, 5), 256, SMEMSZ>>>(inp, gamma, out);
}

// round 16
// speedup vs baseline: 1.1901x; 1.0641x over previous
#include <cuda_runtime.h>
#include <cuda_bf16.h>
#include <math.h>

#define B_ 8
#define N_ 5
#define C_ 256
#define HW_ 4096
#define M_ 32768
#define STG_ (8704 + 10240)
#define SMEMSZ (4 * STG_)   // 4-stage X + W

// ---------------- scratch ----------------------------------------------------
__device__ __nv_bfloat16  g_mtb  [N_*B_*C_*HW_];   // [i][b][c][hw]
__device__ __nv_bfloat16  g_htb  [B_*N_*C_*HW_];   // [b][i][c][hw]
__device__ __nv_bfloat16  g_rhb  [N_*B_*C_*HW_];   // [i][b][c][hw]
__device__ __nv_bfloat16  g_u    [N_*B_*C_*HW_];
__device__ __nv_bfloat16  g_Wcatb[512*512];        // [u;r] x [mt|ht]
__device__ __nv_bfloat16  g_Wob  [256*512];        // full w_o (left|right)
__device__ float          g_bcat [768];

// ---------------- asm helpers ------------------------------------------------
__device__ __forceinline__ void ldsmx4(unsigned &r0, unsigned &r1, unsigned &r2, unsigned &r3, unsigned a) {
    asm volatile("ldmatrix.sync.aligned.m8n8.x4.shared.b16 {%0,%1,%2,%3},[%4];"
        : "=r"(r0), "=r"(r1), "=r"(r2), "=r"(r3) : "r"(a));
}
__device__ __forceinline__ void ldsmx4t(unsigned &r0, unsigned &r1, unsigned &r2, unsigned &r3, unsigned a) {
    asm volatile("ldmatrix.sync.aligned.m8n8.x4.trans.shared.b16 {%0,%1,%2,%3},[%4];"
        : "=r"(r0), "=r"(r1), "=r"(r2), "=r"(r3) : "r"(a));
}
__device__ __forceinline__ void mma_bf16(float* d, const unsigned* a, unsigned b0, unsigned b1) {
    asm volatile("mma.sync.aligned.m16n8k16.row.col.f32.bf16.bf16.f32 "
        "{%0,%1,%2,%3},{%4,%5,%6,%7},{%8,%9},{%0,%1,%2,%3};"
        : "+f"(d[0]), "+f"(d[1]), "+f"(d[2]), "+f"(d[3])
        : "r"(a[0]), "r"(a[1]), "r"(a[2]), "r"(a[3]), "r"(b0), "r"(b1));
}
#define CPA16(dst, src) asm volatile("cp.async.cg.shared.global [%0],[%1],16;" :: "r"(dst), "l"(src))
#define CPCOMMIT()      asm volatile("cp.async.commit_group;" ::: "memory")
#define CPWAIT2()       asm volatile("cp.async.wait_group 2;" ::: "memory")

// ---------------- prep: weights -> bf16 --------------------------------------
__global__ void prep_kernel(const float* __restrict__ wu, const float* __restrict__ wr,
                            const float* __restrict__ wo, const float* __restrict__ bu,
                            const float* __restrict__ br, const float* __restrict__ bo) {
    int idx = blockIdx.x * 256 + threadIdx.x;
    if (idx < 512 * 512) {
        int o = idx >> 9, k = idx & 511;
        float v = (o < 256) ? wu[o * 512 + k] : wr[(o - 256) * 512 + k];
        g_Wcatb[idx] = __float2bfloat16(v);
    }
    if (idx < 256 * 512)
        g_Wob[idx] = __float2bfloat16(wo[idx]);
    if (idx < 768)
        g_bcat[idx] = (idx < 256) ? bu[idx] : (idx < 512 ? br[idx - 256] : bo[idx - 512]);
}

// ---------------- fused front: proj + gates + htb + mtb ----------------------
// 128 blocks x 512 thr. px=tid&255, half=tid>>8 owns 128 channels.
// Phase 1: read inp, accumulate pj, emit htb(bf16).
// Reduce pj across halves (smem), compute the 20 per-pixel gates.
// Phase 2: re-read own htb slice (L2-hot), s = sum_j ht_j, emit mtb(bf16).
__global__ __launch_bounds__(512)
void front_kernel(const float* __restrict__ inp, const float* __restrict__ wgt_w) {
    __shared__ float wsm[4 * 256];
    __shared__ float red[20 * 256];
    const int tid = threadIdx.x;
    const int px  = tid & 255;
    const int half = tid >> 8;
    for (int t = tid; t < 1024; t += 512) wsm[t] = wgt_w[t];
    __syncthreads();
    const int m  = blockIdx.x * 256 + px;
    const int b  = m >> 12;
    const int hw = m & 4095;

    float pj[N_][4];
#pragma unroll
    for (int j = 0; j < N_; j++)
#pragma unroll
        for (int p = 0; p < 4; p++) pj[j][p] = 0.f;

    const float* base = inp + (size_t)b * N_ * C_ * HW_ + hw;
    const int c0 = half * 128;
#pragma unroll 2
    for (int cc = 0; cc < 128; cc++) {
        int c = c0 + cc;
        float w0 = wsm[c], w1 = wsm[256 + c], w2 = wsm[512 + c], w3 = wsm[768 + c];
#pragma unroll
        for (int j = 0; j < N_; j++) {
            float v = base[(j * C_ + c) * HW_];
            pj[j][0] += v * w0; pj[j][1] += v * w1;
            pj[j][2] += v * w2; pj[j][3] += v * w3;
            g_htb[((size_t)(b * N_ + j) * C_ + c) * HW_ + hw] = __float2bfloat16(v);
        }
    }
    // cross-half pj reduction -> full pj in red
    if (half) {
#pragma unroll
        for (int j = 0; j < N_; j++)
#pragma unroll
            for (int p = 0; p < 4; p++)
                red[(j * 4 + p) * 256 + px] = pj[j][p];
    }
    __syncthreads();
    if (!half) {
#pragma unroll
        for (int j = 0; j < N_; j++)
#pragma unroll
            for (int p = 0; p < 4; p++) {
                pj[j][p] += red[(j * 4 + p) * 256 + px];
                red[(j * 4 + p) * 256 + px] = pj[j][p];
            }
    }
    __syncthreads();
    if (half) {
#pragma unroll
        for (int j = 0; j < N_; j++)
#pragma unroll
            for (int p = 0; p < 4; p++)
                pj[j][p] = red[(j * 4 + p) * 256 + px];
    }
    // 20 gates per pixel
    float gate[N_][4];
#pragma unroll
    for (int i = 0; i < N_; i++)
#pragma unroll
        for (int p = 0; p < 4; p++) {
            int jp = (p < i) ? p : p + 1;
            gate[i][p] = 1.f / (1.f + expf(-(pj[i][p] - pj[jp][p])));
        }
    // phase 2: mtb from L2-hot htb
#pragma unroll 2
    for (int cc = 0; cc < 128; cc++) {
        int c = c0 + cc;
        float v[N_], s = 0.f;
#pragma unroll
        for (int j = 0; j < N_; j++) {
            v[j] = __bfloat162float(g_htb[((size_t)(b * N_ + j) * C_ + c) * HW_ + hw]);
            s += v[j];
        }
        int p = c & 3;
#pragma unroll
        for (int i = 0; i < N_; i++)
            g_mtb[((size_t)(i * B_ + b) * C_ + c) * HW_ + hw] =
                __float2bfloat16(gate[i][p] * (s - v[i]));
    }
}

// ---------------- GEMM1 (bf16): [u;rh] = Wcat @ [m_t; h_t] -------------------
// CTA tile 128px x 128ch, 4-stage cp.async ring, 8 warps x (64x32), K=512.
__global__ __launch_bounds__(256, 2)
void gemm1_kernel() {
    extern __shared__ __align__(16) unsigned char smem_dyn[];
    const int tid  = threadIdx.x;
    const int lane = tid & 31, wid = tid >> 5;
    const int wm = wid >> 2, wn = wid & 3;
    const int r_ = lane >> 2, c_ = lane & 3;
    const int i     = blockIdx.z;
    const int nBase = blockIdx.x * 128;
    const int mBase = blockIdx.y * 128;
    const int b = mBase >> 12, hwB = mBase & 4095;

    unsigned sXu = (unsigned)__cvta_generic_to_shared(smem_dyn);
    unsigned sWu = sXu + 4 * 8704;

    const int kr = tid >> 3, c0 = tid & 7;       // X staging
    const int nrow = tid >> 1, ch = tid & 1;     // W staging

    const __nv_bfloat16* mtB = g_mtb + (size_t)(i * B_ + b) * C_ * HW_ + hwB;
    const __nv_bfloat16* htB = g_htb + (size_t)(b * N_ + i) * C_ * HW_ + hwB;
    const __nv_bfloat16* wB  = g_Wcatb + (size_t)(nBase + nrow) * 512;

    auto issue = [&](int tt) {
        int st = tt & 3, kb = tt * 32;
        const __nv_bfloat16* asrc = (kb < 256)
            ? (mtB + (size_t)(kb + kr) * HW_)
            : (htB + (size_t)(kb - 256 + kr) * HW_);
        unsigned xd = sXu + st * 8704 + kr * 272;
        CPA16(xd + c0 * 16,       asrc + c0 * 8);
        CPA16(xd + (c0 + 8) * 16, asrc + (c0 + 8) * 8);
        const __nv_bfloat16* wsrc = wB + kb;
        unsigned wd = sWu + st * 10240 + nrow * 80;
        CPA16(wd + ch * 16,       wsrc + ch * 8);
        CPA16(wd + (ch + 2) * 16, wsrc + (ch + 2) * 8);
    };

    float acc[4][4][4];
#pragma unroll
    for (int mt = 0; mt < 4; mt++)
#pragma unroll
        for (int nt = 0; nt < 4; nt++)
#pragma unroll
            for (int q = 0; q < 4; q++) acc[mt][nt][q] = 0.f;

    const int rowA = (lane & 7) + ((lane >> 4) << 3);
    const int colA = ((lane >> 3) & 1) << 3;
    const unsigned aAddr0 = sXu + rowA * 272 + (wm * 64 + colA) * 2;
    const int nOffB = (((lane >> 4) & 1) << 3) + (lane & 7);
    const int kOffB = ((lane >> 3) & 1) << 3;
    const unsigned bAddr0 = sWu + (wn * 32 + nOffB) * 80 + kOffB * 2;

    const int NK = 16;   // K = 512
#pragma unroll
    for (int tt = 0; tt < 3; tt++) { issue(tt); CPCOMMIT(); }
#pragma unroll 1
    for (int t = 0; t < NK; t++) {
        CPWAIT2();
        __syncthreads();
        if (t + 3 < NK) issue(t + 3);
        CPCOMMIT();
        const int st = t & 3;
        const unsigned aB = aAddr0 + st * 8704;
        const unsigned bB = bAddr0 + st * 10240;
#pragma unroll
        for (int kk = 0; kk < 2; kk++) {
            unsigned af[4][4], bfm[2][4];
#pragma unroll
            for (int mt = 0; mt < 4; mt++)
                ldsmx4t(af[mt][0], af[mt][1], af[mt][2], af[mt][3],
                        aB + kk * (16 * 272) + mt * 32);
#pragma unroll
            for (int np = 0; np < 2; np++)
                ldsmx4(bfm[np][0], bfm[np][1], bfm[np][2], bfm[np][3],
                       bB + kk * 32 + np * (16 * 80));
#pragma unroll
            for (int mt = 0; mt < 4; mt++)
#pragma unroll
                for (int nt = 0; nt < 4; nt++)
                    mma_bf16(acc[mt][nt], af[mt],
                             bfm[nt >> 1][(nt & 1) * 2], bfm[nt >> 1][(nt & 1) * 2 + 1]);
        }
    }

    const int seg = nBase >> 8;   // 0=u, 1=rh
    const size_t obase = (size_t)(i * B_ + b) * C_;
    const size_t hbase = (size_t)(b * N_ + i) * C_;
#pragma unroll
    for (int mt = 0; mt < 4; mt++)
#pragma unroll
        for (int nt = 0; nt < 4; nt++) {
            int px0 = hwB + wm * 64 + mt * 16 + r_;
            int ch0 = nBase + wn * 32 + nt * 8 + c_ * 2;
#pragma unroll
            for (int q = 0; q < 4; q++) {
                int o  = ch0 + (q & 1);
                int hw = px0 + ((q >> 1) << 3);
                float v = acc[mt][nt][q] + g_bcat[o];
                if (seg == 0) {
                    g_u[(obase + o) * HW_ + hw] = __float2bfloat16(1.f / (1.f + expf(-v)));
                } else {
                    int c = o - 256;
                    float ht = __bfloat162float(g_htb[(hbase + c) * HW_ + hw]);
                    g_rhb[(obase + c) * HW_ + hw] = __float2bfloat16(ht / (1.f + expf(-v)));
                }
            }
        }
}

// ---------------- GEMM2 (bf16): o_pre = Wo @ [m_t; rh] + b_o; combine --------
__global__ __launch_bounds__(256, 2)
void gemm2_kernel(const float* __restrict__ inp, const float* __restrict__ gamma,
                  float* __restrict__ out) {
    extern __shared__ __align__(16) unsigned char smem_dyn[];
    const int tid  = threadIdx.x;
    const int lane = tid & 31, wid = tid >> 5;
    const int wm = wid >> 2, wn = wid & 3;
    const int r_ = lane >> 2, c_ = lane & 3;
    const int i     = blockIdx.z;
    const int nBase = blockIdx.x * 128;
    const int mBase = blockIdx.y * 128;
    const int b = mBase >> 12, hwB = mBase & 4095;

    unsigned sXu = (unsigned)__cvta_generic_to_shared(smem_dyn);
    unsigned sWu = sXu + 4 * 8704;

    const int kr = tid >> 3, c0 = tid & 7;
    const int nrow = tid >> 1, ch = tid & 1;

    const __nv_bfloat16* mtB = g_mtb + (size_t)(i * B_ + b) * C_ * HW_ + hwB;
    const __nv_bfloat16* rhB = g_rhb + (size_t)(i * B_ + b) * C_ * HW_ + hwB;
    const __nv_bfloat16* wB  = g_Wob + (size_t)(nBase + nrow) * 512;

    auto issue = [&](int tt) {
        int st = tt & 3, kb = tt * 32;
        const __nv_bfloat16* asrc = (kb < 256)
            ? (mtB + (size_t)(kb + kr) * HW_)
            : (rhB + (size_t)(kb - 256 + kr) * HW_);
        unsigned xd = sXu + st * 8704 + kr * 272;
        CPA16(xd + c0 * 16,       asrc + c0 * 8);
        CPA16(xd + (c0 + 8) * 16, asrc + (c0 + 8) * 8);
        const __nv_bfloat16* wsrc = wB + kb;
        unsigned wd = sWu + st * 10240 + nrow * 80;
        CPA16(wd + ch * 16,       wsrc + ch * 8);
        CPA16(wd + (ch + 2) * 16, wsrc + (ch + 2) * 8);
    };

    float acc[4][4][4];
#pragma unroll
    for (int mt = 0; mt < 4; mt++)
#pragma unroll
        for (int nt = 0; nt < 4; nt++)
#pragma unroll
            for (int q = 0; q < 4; q++) acc[mt][nt][q] = 0.f;

    const int rowA = (lane & 7) + ((lane >> 4) << 3);
    const int colA = ((lane >> 3) & 1) << 3;
    const unsigned aAddr0 = sXu + rowA * 272 + (wm * 64 + colA) * 2;
    const int nOffB = (((lane >> 4) & 1) << 3) + (lane & 7);
    const int kOffB = ((lane >> 3) & 1) << 3;
    const unsigned bAddr0 = sWu + (wn * 32 + nOffB) * 80 + kOffB * 2;

    const int NK = 16;   // K = 512: [m_t ; rh]
#pragma unroll
    for (int tt = 0; tt < 3; tt++) { issue(tt); CPCOMMIT(); }
#pragma unroll 1
    for (int t = 0; t < NK; t++) {
        CPWAIT2();
        __syncthreads();
        if (t + 3 < NK) issue(t + 3);
        CPCOMMIT();
        const int st = t & 3;
        const unsigned aB = aAddr0 + st * 8704;
        const unsigned bB = bAddr0 + st * 10240;
#pragma unroll
        for (int kk = 0; kk < 2; kk++) {
            unsigned af[4][4], bfm[2][4];
#pragma unroll
            for (int mt = 0; mt < 4; mt++)
                ldsmx4t(af[mt][0], af[mt][1], af[mt][2], af[mt][3],
                        aB + kk * (16 * 272) + mt * 32);
#pragma unroll
            for (int np = 0; np < 2; np++)
                ldsmx4(bfm[np][0], bfm[np][1], bfm[np][2], bfm[np][3],
                       bB + kk * 32 + np * (16 * 80));
#pragma unroll
            for (int mt = 0; mt < 4; mt++)
#pragma unroll
                for (int nt = 0; nt < 4; nt++)
                    mma_bf16(acc[mt][nt], af[mt],
                             bfm[nt >> 1][(nt & 1) * 2], bfm[nt >> 1][(nt & 1) * 2 + 1]);
        }
    }

    const float gm = gamma[0];
    const float* htf = inp + (size_t)(b * N_ + i) * C_ * HW_;
    const size_t obase = (size_t)(i * B_ + b) * C_;
#pragma unroll
    for (int mt = 0; mt < 4; mt++)
#pragma unroll
        for (int nt = 0; nt < 4; nt++) {
            int px0 = hwB + wm * 64 + mt * 16 + r_;
            int ch0 = nBase + wn * 32 + nt * 8 + c_ * 2;
#pragma unroll
            for (int q = 0; q < 4; q++) {
                int o  = ch0 + (q & 1);
                int hw = px0 + ((q >> 1) << 3);
                size_t idx = (obase + o) * HW_ + hw;
                float opre = acc[mt][nt][q] + g_bcat[512 + o];
                float u  = __bfloat162float(g_u[idx]);
                float ht = htf[(size_t)o * HW_ + hw];
                float hn = ht * (1.f - u) + tanhf(opre) * u;
                out[((size_t)(b * N_ + i) * C_ + o) * HW_ + hw] = hn * gm + ht;
            }
        }
}

// ---------------- launch (single stream) -------------------------------------
extern "C" void kernel_launch(void* const* d_in, const int* in_sizes, int n_in,
                              void* d_out, int out_size) {
    const float* inp   = (const float*)d_in[0];
    const float* wgt_w = (const float*)d_in[1];
    const float* w_r   = (const float*)d_in[2];
    const float* b_r   = (const float*)d_in[3];
    const float* w_u   = (const float*)d_in[4];
    const float* b_u   = (const float*)d_in[5];
    const float* w_o   = (const float*)d_in[6];
    const float* b_o   = (const float*)d_in[7];
    const float* gamma = (const float*)d_in[8];
    float* out = (float*)d_out;

    cudaFuncSetAttribute(gemm1_kernel, cudaFuncAttributeMaxDynamicSharedMemorySize, SMEMSZ);
    cudaFuncSetAttribute(gemm2_kernel, cudaFuncAttributeMaxDynamicSharedMemorySize, SMEMSZ);

    prep_kernel<<<1024, 256>>>(w_u, w_r, w_o, b_u, b_r, b_o);
    front_kernel<<<M_ / 256, 512>>>(inp, wgt_w);
    gemm1_kernel<<<dim3(4, 256, 5), 256, SMEMSZ>>>();
    gemm2_kernel<<<dim3(2, 256, 5), 256, SMEMSZ>>>(inp, gamma, out);
}

// round 17
// speedup vs baseline: 1.3612x; 1.1438x over previous
#include <cuda_runtime.h>
#include <cuda_bf16.h>
#include <math.h>

#define B_ 8
#define N_ 5
#define C_ 256
#define HW_ 4096
#define M_ 32768
#define STG_ (8704 + 10240)
#define SMEMSZ1 (4 * STG_)              // gemm1: 4-stage X + W
#define SMEMSZ2 (4 * STG_ + 64*256*2)   // gemm2: stages + u stash (32KB)

// ---------------- scratch ----------------------------------------------------
__device__ __nv_bfloat16  g_mtb  [N_*B_*C_*HW_];   // [i][b][c][hw]
__device__ __nv_bfloat16  g_htb  [B_*N_*C_*HW_];   // [b][i][c][hw]
__device__ __nv_bfloat16  g_rhb  [N_*B_*C_*HW_];   // [i][b][c][hw]
__device__ __nv_bfloat16  g_Wcatb[512*512];        // [u;r] x [mt|ht]
__device__ __nv_bfloat16  g_Wob  [256*512];        // full w_o (left|right)
__device__ float          g_bcat [768];

// ---------------- asm helpers ------------------------------------------------
__device__ __forceinline__ void ldsmx4(unsigned &r0, unsigned &r1, unsigned &r2, unsigned &r3, unsigned a) {
    asm volatile("ldmatrix.sync.aligned.m8n8.x4.shared.b16 {%0,%1,%2,%3},[%4];"
        : "=r"(r0), "=r"(r1), "=r"(r2), "=r"(r3) : "r"(a));
}
__device__ __forceinline__ void ldsmx4t(unsigned &r0, unsigned &r1, unsigned &r2, unsigned &r3, unsigned a) {
    asm volatile("ldmatrix.sync.aligned.m8n8.x4.trans.shared.b16 {%0,%1,%2,%3},[%4];"
        : "=r"(r0), "=r"(r1), "=r"(r2), "=r"(r3) : "r"(a));
}
__device__ __forceinline__ void mma_bf16(float* d, const unsigned* a, unsigned b0, unsigned b1) {
    asm volatile("mma.sync.aligned.m16n8k16.row.col.f32.bf16.bf16.f32 "
        "{%0,%1,%2,%3},{%4,%5,%6,%7},{%8,%9},{%0,%1,%2,%3};"
        : "+f"(d[0]), "+f"(d[1]), "+f"(d[2]), "+f"(d[3])
        : "r"(a[0]), "r"(a[1]), "r"(a[2]), "r"(a[3]), "r"(b0), "r"(b1));
}
#define CPA16(dst, src) asm volatile("cp.async.cg.shared.global [%0],[%1],16;" :: "r"(dst), "l"(src))
#define CPCOMMIT()      asm volatile("cp.async.commit_group;" ::: "memory")
#define CPWAIT2()       asm volatile("cp.async.wait_group 2;" ::: "memory")
#define CPWAIT0()       asm volatile("cp.async.wait_group 0;" ::: "memory")

// ---------------- prep: weights -> bf16 --------------------------------------
__global__ void prep_kernel(const float* __restrict__ wu, const float* __restrict__ wr,
                            const float* __restrict__ wo, const float* __restrict__ bu,
                            const float* __restrict__ br, const float* __restrict__ bo) {
    int idx = blockIdx.x * 256 + threadIdx.x;
    if (idx < 512 * 512) {
        int o = idx >> 9, k = idx & 511;
        float v = (o < 256) ? wu[o * 512 + k] : wr[(o - 256) * 512 + k];
        g_Wcatb[idx] = __float2bfloat16(v);
    }
    if (idx < 256 * 512)
        g_Wob[idx] = __float2bfloat16(wo[idx]);
    if (idx < 768)
        g_bcat[idx] = (idx < 256) ? bu[idx] : (idx < 512 ? br[idx - 256] : bo[idx - 512]);
}

// ---------------- fused front: proj + gates + htb + mtb ----------------------
__global__ __launch_bounds__(512)
void front_kernel(const float* __restrict__ inp, const float* __restrict__ wgt_w) {
    __shared__ float wsm[4 * 256];
    __shared__ float red[20 * 256];
    const int tid = threadIdx.x;
    const int px  = tid & 255;
    const int half = tid >> 8;
    for (int t = tid; t < 1024; t += 512) wsm[t] = wgt_w[t];
    __syncthreads();
    const int m  = blockIdx.x * 256 + px;
    const int b  = m >> 12;
    const int hw = m & 4095;

    float pj[N_][4];
#pragma unroll
    for (int j = 0; j < N_; j++)
#pragma unroll
        for (int p = 0; p < 4; p++) pj[j][p] = 0.f;

    const float* base = inp + (size_t)b * N_ * C_ * HW_ + hw;
    const int c0 = half * 128;
#pragma unroll 2
    for (int cc = 0; cc < 128; cc++) {
        int c = c0 + cc;
        float w0 = wsm[c], w1 = wsm[256 + c], w2 = wsm[512 + c], w3 = wsm[768 + c];
#pragma unroll
        for (int j = 0; j < N_; j++) {
            float v = base[(j * C_ + c) * HW_];
            pj[j][0] += v * w0; pj[j][1] += v * w1;
            pj[j][2] += v * w2; pj[j][3] += v * w3;
            g_htb[((size_t)(b * N_ + j) * C_ + c) * HW_ + hw] = __float2bfloat16(v);
        }
    }
    if (half) {
#pragma unroll
        for (int j = 0; j < N_; j++)
#pragma unroll
            for (int p = 0; p < 4; p++)
                red[(j * 4 + p) * 256 + px] = pj[j][p];
    }
    __syncthreads();
    if (!half) {
#pragma unroll
        for (int j = 0; j < N_; j++)
#pragma unroll
            for (int p = 0; p < 4; p++) {
                pj[j][p] += red[(j * 4 + p) * 256 + px];
                red[(j * 4 + p) * 256 + px] = pj[j][p];
            }
    }
    __syncthreads();
    if (half) {
#pragma unroll
        for (int j = 0; j < N_; j++)
#pragma unroll
            for (int p = 0; p < 4; p++)
                pj[j][p] = red[(j * 4 + p) * 256 + px];
    }
    float gate[N_][4];
#pragma unroll
    for (int i = 0; i < N_; i++)
#pragma unroll
        for (int p = 0; p < 4; p++) {
            int jp = (p < i) ? p : p + 1;
            gate[i][p] = 1.f / (1.f + expf(-(pj[i][p] - pj[jp][p])));
        }
#pragma unroll 2
    for (int cc = 0; cc < 128; cc++) {
        int c = c0 + cc;
        float v[N_], s = 0.f;
#pragma unroll
        for (int j = 0; j < N_; j++) {
            v[j] = __bfloat162float(g_htb[((size_t)(b * N_ + j) * C_ + c) * HW_ + hw]);
            s += v[j];
        }
        int p = c & 3;
#pragma unroll
        for (int i = 0; i < N_; i++)
            g_mtb[((size_t)(i * B_ + b) * C_ + c) * HW_ + hw] =
                __float2bfloat16(gate[i][p] * (s - v[i]));
    }
}

// ---------------- GEMM1 (bf16): rh = ht*sigmoid(Wr@[mt;ht]) ------------------
// CTA tile 128px x 128ch (r chans only), 4-stage ring, 8 warps x (64x32).
__global__ __launch_bounds__(256, 2)
void gemm1_kernel() {
    extern __shared__ __align__(16) unsigned char smem_dyn[];
    const int tid  = threadIdx.x;
    const int lane = tid & 31, wid = tid >> 5;
    const int wm = wid >> 2, wn = wid & 3;
    const int r_ = lane >> 2, c_ = lane & 3;
    const int i     = blockIdx.z;
    const int nBase = blockIdx.x * 128;        // 0 or 128 (r channels)
    const int mBase = blockIdx.y * 128;
    const int b = mBase >> 12, hwB = mBase & 4095;

    unsigned sXu = (unsigned)__cvta_generic_to_shared(smem_dyn);
    unsigned sWu = sXu + 4 * 8704;

    const int kr = tid >> 3, c0 = tid & 7;
    const int nrow = tid >> 1, ch = tid & 1;

    const __nv_bfloat16* mtB = g_mtb + (size_t)(i * B_ + b) * C_ * HW_ + hwB;
    const __nv_bfloat16* htB = g_htb + (size_t)(b * N_ + i) * C_ * HW_ + hwB;
    const __nv_bfloat16* wB  = g_Wcatb + (size_t)(256 + nBase + nrow) * 512;  // Wr rows

    auto issue = [&](int tt) {
        int st = tt & 3, kb = tt * 32;
        const __nv_bfloat16* asrc = (kb < 256)
            ? (mtB + (size_t)(kb + kr) * HW_)
            : (htB + (size_t)(kb - 256 + kr) * HW_);
        unsigned xd = sXu + st * 8704 + kr * 272;
        CPA16(xd + c0 * 16,       asrc + c0 * 8);
        CPA16(xd + (c0 + 8) * 16, asrc + (c0 + 8) * 8);
        const __nv_bfloat16* wsrc = wB + kb;
        unsigned wd = sWu + st * 10240 + nrow * 80;
        CPA16(wd + ch * 16,       wsrc + ch * 8);
        CPA16(wd + (ch + 2) * 16, wsrc + (ch + 2) * 8);
    };

    float acc[4][4][4];
#pragma unroll
    for (int mt = 0; mt < 4; mt++)
#pragma unroll
        for (int nt = 0; nt < 4; nt++)
#pragma unroll
            for (int q = 0; q < 4; q++) acc[mt][nt][q] = 0.f;

    const int rowA = (lane & 7) + ((lane >> 4) << 3);
    const int colA = ((lane >> 3) & 1) << 3;
    const unsigned aAddr0 = sXu + rowA * 272 + (wm * 64 + colA) * 2;
    const int nOffB = (((lane >> 4) & 1) << 3) + (lane & 7);
    const int kOffB = ((lane >> 3) & 1) << 3;
    const unsigned bAddr0 = sWu + (wn * 32 + nOffB) * 80 + kOffB * 2;

    const int NK = 16;
#pragma unroll
    for (int tt = 0; tt < 3; tt++) { issue(tt); CPCOMMIT(); }
#pragma unroll 1
    for (int t = 0; t < NK; t++) {
        CPWAIT2();
        __syncthreads();
        if (t + 3 < NK) issue(t + 3);
        CPCOMMIT();
        const int st = t & 3;
        const unsigned aB = aAddr0 + st * 8704;
        const unsigned bB = bAddr0 + st * 10240;
#pragma unroll
        for (int kk = 0; kk < 2; kk++) {
            unsigned af[4][4], bfm[2][4];
#pragma unroll
            for (int mt = 0; mt < 4; mt++)
                ldsmx4t(af[mt][0], af[mt][1], af[mt][2], af[mt][3],
                        aB + kk * (16 * 272) + mt * 32);
#pragma unroll
            for (int np = 0; np < 2; np++)
                ldsmx4(bfm[np][0], bfm[np][1], bfm[np][2], bfm[np][3],
                       bB + kk * 32 + np * (16 * 80));
#pragma unroll
            for (int mt = 0; mt < 4; mt++)
#pragma unroll
                for (int nt = 0; nt < 4; nt++)
                    mma_bf16(acc[mt][nt], af[mt],
                             bfm[nt >> 1][(nt & 1) * 2], bfm[nt >> 1][(nt & 1) * 2 + 1]);
        }
    }

    const size_t obase = (size_t)(i * B_ + b) * C_;
    const size_t hbase = (size_t)(b * N_ + i) * C_;
#pragma unroll
    for (int mt = 0; mt < 4; mt++)
#pragma unroll
        for (int nt = 0; nt < 4; nt++) {
            int px0 = hwB + wm * 64 + mt * 16 + r_;
            int ch0 = nBase + wn * 32 + nt * 8 + c_ * 2;
#pragma unroll
            for (int q = 0; q < 4; q++) {
                int c  = ch0 + (q & 1);
                int hw = px0 + ((q >> 1) << 3);
                float v = acc[mt][nt][q] + g_bcat[256 + c];
                float ht = __bfloat162float(g_htb[(hbase + c) * HW_ + hw]);
                g_rhb[(obase + c) * HW_ + hw] = __float2bfloat16(ht / (1.f + expf(-v)));
            }
        }
}

// ---------------- GEMM2: u (smem) then o_pre; combine ------------------------
// loop1: u_pre = Wu@[mt;ht]; u -> smem stash. loop2: o_pre = Wo@[mt;rh].
__global__ __launch_bounds__(256, 2)
void gemm2_kernel(const float* __restrict__ inp, const float* __restrict__ gamma,
                  float* __restrict__ out) {
    extern __shared__ __align__(16) unsigned char smem_dyn[];
    const int tid  = threadIdx.x;
    const int lane = tid & 31, wid = tid >> 5;
    const int wm = wid >> 2, wn = wid & 3;
    const int r_ = lane >> 2, c_ = lane & 3;
    const int i     = blockIdx.z;
    const int nBase = blockIdx.x * 128;
    const int mBase = blockIdx.y * 128;
    const int b = mBase >> 12, hwB = mBase & 4095;

    unsigned sXu = (unsigned)__cvta_generic_to_shared(smem_dyn);
    unsigned sWu = sXu + 4 * 8704;
    __nv_bfloat16* u_s = (__nv_bfloat16*)(smem_dyn + 4 * STG_);

    const int kr = tid >> 3, c0 = tid & 7;
    const int nrow = tid >> 1, ch = tid & 1;

    const __nv_bfloat16* mtB = g_mtb + (size_t)(i * B_ + b) * C_ * HW_ + hwB;
    const __nv_bfloat16* htB = g_htb + (size_t)(b * N_ + i) * C_ * HW_ + hwB;
    const __nv_bfloat16* rhB = g_rhb + (size_t)(i * B_ + b) * C_ * HW_ + hwB;

    float acc[4][4][4];
    const int rowA = (lane & 7) + ((lane >> 4) << 3);
    const int colA = ((lane >> 3) & 1) << 3;
    const unsigned aAddr0 = sXu + rowA * 272 + (wm * 64 + colA) * 2;
    const int nOffB = (((lane >> 4) & 1) << 3) + (lane & 7);
    const int kOffB = ((lane >> 3) & 1) << 3;
    const unsigned bAddr0 = sWu + (wn * 32 + nOffB) * 80 + kOffB * 2;

    auto issue = [&](int tt, const __nv_bfloat16* aHi, const __nv_bfloat16* wM) {
        int st = tt & 3, kb = tt * 32;
        const __nv_bfloat16* asrc = (kb < 256)
            ? (mtB + (size_t)(kb + kr) * HW_)
            : (aHi + (size_t)(kb - 256 + kr) * HW_);
        unsigned xd = sXu + st * 8704 + kr * 272;
        CPA16(xd + c0 * 16,       asrc + c0 * 8);
        CPA16(xd + (c0 + 8) * 16, asrc + (c0 + 8) * 8);
        const __nv_bfloat16* wsrc = wM + (size_t)(nBase + nrow) * 512 + kb;
        unsigned wd = sWu + st * 10240 + nrow * 80;
        CPA16(wd + ch * 16,       wsrc + ch * 8);
        CPA16(wd + (ch + 2) * 16, wsrc + (ch + 2) * 8);
    };

    auto mainloop = [&](const __nv_bfloat16* aHi, const __nv_bfloat16* wM) {
#pragma unroll
        for (int mt = 0; mt < 4; mt++)
#pragma unroll
            for (int nt = 0; nt < 4; nt++)
#pragma unroll
                for (int q = 0; q < 4; q++) acc[mt][nt][q] = 0.f;
#pragma unroll
        for (int tt = 0; tt < 3; tt++) { issue(tt, aHi, wM); CPCOMMIT(); }
#pragma unroll 1
        for (int t = 0; t < 16; t++) {
            CPWAIT2();
            __syncthreads();
            if (t + 3 < 16) issue(t + 3, aHi, wM);
            CPCOMMIT();
            const int st = t & 3;
            const unsigned aB = aAddr0 + st * 8704;
            const unsigned bB = bAddr0 + st * 10240;
#pragma unroll
            for (int kk = 0; kk < 2; kk++) {
                unsigned af[4][4], bfm[2][4];
#pragma unroll
                for (int mt = 0; mt < 4; mt++)
                    ldsmx4t(af[mt][0], af[mt][1], af[mt][2], af[mt][3],
                            aB + kk * (16 * 272) + mt * 32);
#pragma unroll
                for (int np = 0; np < 2; np++)
                    ldsmx4(bfm[np][0], bfm[np][1], bfm[np][2], bfm[np][3],
                           bB + kk * 32 + np * (16 * 80));
#pragma unroll
                for (int mt = 0; mt < 4; mt++)
#pragma unroll
                    for (int nt = 0; nt < 4; nt++)
                        mma_bf16(acc[mt][nt], af[mt],
                                 bfm[nt >> 1][(nt & 1) * 2], bfm[nt >> 1][(nt & 1) * 2 + 1]);
            }
        }
        CPWAIT0();
        __syncthreads();
    };

    // ---- loop1: u = sigmoid(Wu@[mt;ht] + bu) -> smem stash ----
    mainloop(htB, g_Wcatb);
#pragma unroll
    for (int mt = 0; mt < 4; mt++)
#pragma unroll
        for (int nt = 0; nt < 4; nt++) {
            int ch0 = nBase + wn * 32 + nt * 8 + c_ * 2;
#pragma unroll
            for (int q = 0; q < 4; q++) {
                int o = ch0 + (q & 1);
                float v = acc[mt][nt][q] + g_bcat[o];
                u_s[(mt * 16 + nt * 4 + q) * 256 + tid] =
                    __float2bfloat16(1.f / (1.f + expf(-v)));
            }
        }

    // ---- loop2: o_pre = Wo@[mt;rh] + bo; combine ----
    mainloop(rhB, g_Wob);
    const float gm = gamma[0];
    const float* htf = inp + (size_t)(b * N_ + i) * C_ * HW_;
#pragma unroll
    for (int mt = 0; mt < 4; mt++)
#pragma unroll
        for (int nt = 0; nt < 4; nt++) {
            int px0 = hwB + wm * 64 + mt * 16 + r_;
            int ch0 = nBase + wn * 32 + nt * 8 + c_ * 2;
#pragma unroll
            for (int q = 0; q < 4; q++) {
                int o  = ch0 + (q & 1);
                int hw = px0 + ((q >> 1) << 3);
                float opre = acc[mt][nt][q] + g_bcat[512 + o];
                float u  = __bfloat162float(u_s[(mt * 16 + nt * 4 + q) * 256 + tid]);
                float ht = htf[(size_t)o * HW_ + hw];
                float hn = ht * (1.f - u) + tanhf(opre) * u;
                out[((size_t)(b * N_ + i) * C_ + o) * HW_ + hw] = hn * gm + ht;
            }
        }
}

// ---------------- launch (single stream) -------------------------------------
extern "C" void kernel_launch(void* const* d_in, const int* in_sizes, int n_in,
                              void* d_out, int out_size) {
    const float* inp   = (const float*)d_in[0];
    const float* wgt_w = (const float*)d_in[1];
    const float* w_r   = (const float*)d_in[2];
    const float* b_r   = (const float*)d_in[3];
    const float* w_u   = (const float*)d_in[4];
    const float* b_u   = (const float*)d_in[5];
    const float* w_o   = (const float*)d_in[6];
    const float* b_o   = (const float*)d_in[7];
    const float* gamma = (const float*)d_in[8];
    float* out = (float*)d_out;

    cudaFuncSetAttribute(gemm1_kernel, cudaFuncAttributeMaxDynamicSharedMemorySize, SMEMSZ1);
    cudaFuncSetAttribute(gemm2_kernel, cudaFuncAttributeMaxDynamicSharedMemorySize, SMEMSZ2);

    prep_kernel<<<1024, 256>>>(w_u, w_r, w_o, b_u, b_r, b_o);
    front_kernel<<<M_ / 256, 512>>>(inp, wgt_w);
    gemm1_kernel<<<dim3(2, 256, 5), 256, SMEMSZ1>>>();
    gemm2_kernel<<<dim3(2, 256, 5), 256, SMEMSZ2>>>(inp, gamma, out);
}